// round 7
// baseline (speedup 1.0000x reference)
#include <cuda_runtime.h>
#include <cstddef>

#define N_NODES_MAX 100000
#define IN_CH 256
#define OUT_CH 128

// Scratch for xw = x @ W  (51.2 MB, static device array: no allocations)
__device__ float g_xw[(size_t)N_NODES_MAX * OUT_CH];

// ---------------------------------------------------------------------------
// Kernel 1: out[n, c] = bias[c]
// ---------------------------------------------------------------------------
__global__ void init_out_kernel(float4* __restrict__ out,
                                const float4* __restrict__ bias, int n4) {
    int i = blockIdx.x * blockDim.x + threadIdx.x;
    if (i < n4) out[i] = bias[i & (OUT_CH / 4 - 1)];
}

// ---------------------------------------------------------------------------
// Kernel 2: g_xw = x @ W   (M x 256) @ (256 x 128), fp32
// Tile: BM=64, BN=128, BK=32. 256 threads, each computes 8x4.
// A-tile stored transposed [BK][BM] with XOR swizzle on the row index so that
// the transposed scalar stores are bank-conflict-free while reads stay
// float4-aligned warp-uniform broadcasts.
// ---------------------------------------------------------------------------
#define BM 64
#define BN 128
#define BK 32

__global__ __launch_bounds__(256, 2) void gemm_kernel(
    const float* __restrict__ x, const float* __restrict__ w, int M) {
    __shared__ __align__(16) float As[BK][BM];
    __shared__ __align__(16) float Bs[BK][BN];

    const int t  = threadIdx.x;
    const int tx = t & 31;   // column group (4 cols each)
    const int ty = t >> 5;   // row group (8 rows each)
    const int m0 = blockIdx.x * BM;

    float acc[8][4];
#pragma unroll
    for (int i = 0; i < 8; i++)
#pragma unroll
        for (int j = 0; j < 4; j++) acc[i][j] = 0.f;

    for (int kt = 0; kt < IN_CH; kt += BK) {
        // ---- load x tile: 64 rows x 32 k-values, transposed+swizzled into As
#pragma unroll
        for (int s = 0; s < 2; s++) {
            int idx = t + s * 256;          // 0..511
            int r   = idx >> 3;             // 0..63  (row within tile)
            int c4  = idx & 7;              // 0..7   (float4 index along k)
            float4 v = make_float4(0.f, 0.f, 0.f, 0.f);
            int gr = m0 + r;
            if (gr < M)
                v = *reinterpret_cast<const float4*>(
                        x + (size_t)gr * IN_CH + kt + c4 * 4);
            // element (k = c4*4+q, row r) stored at As[k][ r ^ ((k>>2)<<2) ]
            int col = r ^ (c4 << 2);
            As[c4 * 4 + 0][col] = v.x;
            As[c4 * 4 + 1][col] = v.y;
            As[c4 * 4 + 2][col] = v.z;
            As[c4 * 4 + 3][col] = v.w;
        }
        // ---- load w tile: 32 k-rows x 128 cols (natural layout)
#pragma unroll
        for (int s = 0; s < 4; s++) {
            int idx = t + s * 256;          // 0..1023
            int kk  = idx >> 5;             // 0..31
            int q   = idx & 31;             // 0..31 (float4 index along n)
            *reinterpret_cast<float4*>(&Bs[kk][q * 4]) =
                *reinterpret_cast<const float4*>(
                    w + (size_t)(kt + kk) * OUT_CH + q * 4);
        }
        __syncthreads();

#pragma unroll
        for (int kk = 0; kk < BK; kk++) {
            int sw = (kk >> 2) << 2;  // swizzle term, 0..28 (bits 2..4)
            float4 a0 = *reinterpret_cast<const float4*>(
                            &As[kk][(ty * 8 + 0) ^ sw]);
            float4 a1 = *reinterpret_cast<const float4*>(
                            &As[kk][(ty * 8 + 4) ^ sw]);
            float4 b  = *reinterpret_cast<const float4*>(&Bs[kk][tx * 4]);
            float a[8] = {a0.x, a0.y, a0.z, a0.w, a1.x, a1.y, a1.z, a1.w};
#pragma unroll
            for (int i = 0; i < 8; i++) {
                acc[i][0] += a[i] * b.x;
                acc[i][1] += a[i] * b.y;
                acc[i][2] += a[i] * b.z;
                acc[i][3] += a[i] * b.w;
            }
        }
        __syncthreads();
    }

#pragma unroll
    for (int i = 0; i < 8; i++) {
        int gr = m0 + ty * 8 + i;
        if (gr < M)
            *reinterpret_cast<float4*>(g_xw + (size_t)gr * OUT_CH + tx * 4) =
                make_float4(acc[i][0], acc[i][1], acc[i][2], acc[i][3]);
    }
}

// ---------------------------------------------------------------------------
// Kernel 3: edge scatter. One warp per edge: gather xw[dst] (512B coalesced,
// L2-resident), scale by edge_val, RED.E.ADD.F32 into out[src].
// ---------------------------------------------------------------------------
__global__ __launch_bounds__(256) void scatter_kernel(
    const int* __restrict__ esrc, const int* __restrict__ edst,
    const float* __restrict__ eval, float* __restrict__ out, int E) {
    int e = (blockIdx.x * blockDim.x + threadIdx.x) >> 5;
    if (e >= E) return;
    int lane = threadIdx.x & 31;

    int   s = __ldg(esrc + e);
    int   d = __ldg(edst + e);
    float v = __ldg(eval + e);

    float4 m = *reinterpret_cast<const float4*>(
                   g_xw + (size_t)d * OUT_CH + lane * 4);
    float* o = out + (size_t)s * OUT_CH + lane * 4;
    atomicAdd(o + 0, m.x * v);
    atomicAdd(o + 1, m.y * v);
    atomicAdd(o + 2, m.z * v);
    atomicAdd(o + 3, m.w * v);
}

// ---------------------------------------------------------------------------
// Launch
// inputs (metadata order): x[f32 N*256], edge_src[i32 E], edge_dst[i32 E],
//                          edge_vals[f32 E], weight[f32 256*128], bias[f32 128]
// output: f32 N*128
// ---------------------------------------------------------------------------
extern "C" void kernel_launch(void* const* d_in, const int* in_sizes, int n_in,
                              void* d_out, int out_size) {
    const float* x    = (const float*)d_in[0];
    const int*   esrc = (const int*)d_in[1];
    const int*   edst = (const int*)d_in[2];
    const float* eval = (const float*)d_in[3];
    const float* w    = (const float*)d_in[4];
    const float* bias = (const float*)d_in[5];
    float*       out  = (float*)d_out;

    const int N = in_sizes[0] / IN_CH;   // 100000
    const int E = in_sizes[1];           // 3200000

    // 1) out = bias (broadcast); d_out is poisoned, must init.
    int n4 = N * (OUT_CH / 4);
    init_out_kernel<<<(n4 + 255) / 256, 256>>>(
        (float4*)out, (const float4*)bias, n4);

    // 2) g_xw = x @ W
    gemm_kernel<<<(N + BM - 1) / BM, 256>>>(x, w, N);

    // 3) out[src] += xw[dst] * val  (atomic scatter, warp per edge)
    int warps = E;
    scatter_kernel<<<(warps + 7) / 8, 256>>>(esrc, edst, eval, out, E);
}

// round 11
// speedup vs baseline: 1.0030x; 1.0030x over previous
#include <cuda_runtime.h>
#include <cstddef>

#define N_NODES_MAX 100000
#define IN_CH 256
#define OUT_CH 128

// Scratch for xw = x @ W  (51.2 MB, static device array: no allocations)
__device__ float g_xw[(size_t)N_NODES_MAX * OUT_CH];

// ---------------------------------------------------------------------------
// Kernel 1: out[n, c] = bias[c]
// ---------------------------------------------------------------------------
__global__ void init_out_kernel(float4* __restrict__ out,
                                const float4* __restrict__ bias, int n4) {
    int i = blockIdx.x * blockDim.x + threadIdx.x;
    if (i < n4) out[i] = bias[i & (OUT_CH / 4 - 1)];
}

// ---------------------------------------------------------------------------
// Kernel 2: g_xw = x @ W   (M x 256) @ (256 x 128), fp32
// Tile: BM=64, BN=128, BK=32. 256 threads, each computes 8x4.
// A-tile stored transposed [BK][BM] with XOR swizzle on the row index so that
// the transposed scalar stores are bank-conflict-free while reads stay
// float4-aligned warp-uniform broadcasts.
// ---------------------------------------------------------------------------
#define BM 64
#define BN 128
#define BK 32

__global__ __launch_bounds__(256, 2) void gemm_kernel(
    const float* __restrict__ x, const float* __restrict__ w, int M) {
    __shared__ __align__(16) float As[BK][BM];
    __shared__ __align__(16) float Bs[BK][BN];

    const int t  = threadIdx.x;
    const int tx = t & 31;   // column group (4 cols each)
    const int ty = t >> 5;   // row group (8 rows each)
    const int m0 = blockIdx.x * BM;

    float acc[8][4];
#pragma unroll
    for (int i = 0; i < 8; i++)
#pragma unroll
        for (int j = 0; j < 4; j++) acc[i][j] = 0.f;

    for (int kt = 0; kt < IN_CH; kt += BK) {
        // ---- load x tile: 64 rows x 32 k-values, transposed+swizzled into As
#pragma unroll
        for (int s = 0; s < 2; s++) {
            int idx = t + s * 256;          // 0..511
            int r   = idx >> 3;             // 0..63  (row within tile)
            int c4  = idx & 7;              // 0..7   (float4 index along k)
            float4 v = make_float4(0.f, 0.f, 0.f, 0.f);
            int gr = m0 + r;
            if (gr < M)
                v = *reinterpret_cast<const float4*>(
                        x + (size_t)gr * IN_CH + kt + c4 * 4);
            // element (k = c4*4+q, row r) stored at As[k][ r ^ ((k>>2)<<2) ]
            int col = r ^ (c4 << 2);
            As[c4 * 4 + 0][col] = v.x;
            As[c4 * 4 + 1][col] = v.y;
            As[c4 * 4 + 2][col] = v.z;
            As[c4 * 4 + 3][col] = v.w;
        }
        // ---- load w tile: 32 k-rows x 128 cols (natural layout)
#pragma unroll
        for (int s = 0; s < 4; s++) {
            int idx = t + s * 256;          // 0..1023
            int kk  = idx >> 5;             // 0..31
            int q   = idx & 31;             // 0..31 (float4 index along n)
            *reinterpret_cast<float4*>(&Bs[kk][q * 4]) =
                *reinterpret_cast<const float4*>(
                    w + (size_t)(kt + kk) * OUT_CH + q * 4);
        }
        __syncthreads();

#pragma unroll
        for (int kk = 0; kk < BK; kk++) {
            int sw = (kk >> 2) << 2;  // swizzle term, 0..28 (bits 2..4)
            float4 a0 = *reinterpret_cast<const float4*>(
                            &As[kk][(ty * 8 + 0) ^ sw]);
            float4 a1 = *reinterpret_cast<const float4*>(
                            &As[kk][(ty * 8 + 4) ^ sw]);
            float4 b  = *reinterpret_cast<const float4*>(&Bs[kk][tx * 4]);
            float a[8] = {a0.x, a0.y, a0.z, a0.w, a1.x, a1.y, a1.z, a1.w};
#pragma unroll
            for (int i = 0; i < 8; i++) {
                acc[i][0] += a[i] * b.x;
                acc[i][1] += a[i] * b.y;
                acc[i][2] += a[i] * b.z;
                acc[i][3] += a[i] * b.w;
            }
        }
        __syncthreads();
    }

#pragma unroll
    for (int i = 0; i < 8; i++) {
        int gr = m0 + ty * 8 + i;
        if (gr < M)
            *reinterpret_cast<float4*>(g_xw + (size_t)gr * OUT_CH + tx * 4) =
                make_float4(acc[i][0], acc[i][1], acc[i][2], acc[i][3]);
    }
}

// ---------------------------------------------------------------------------
// Kernel 3: edge scatter. One warp per edge: gather xw[dst] (512B coalesced,
// L2-resident), scale by edge_val, RED.E.ADD.F32 into out[src].
// ---------------------------------------------------------------------------
__global__ __launch_bounds__(256) void scatter_kernel(
    const int* __restrict__ esrc, const int* __restrict__ edst,
    const float* __restrict__ eval, float* __restrict__ out, int E) {
    int e = (blockIdx.x * blockDim.x + threadIdx.x) >> 5;
    if (e >= E) return;
    int lane = threadIdx.x & 31;

    int   s = __ldg(esrc + e);
    int   d = __ldg(edst + e);
    float v = __ldg(eval + e);

    float4 m = *reinterpret_cast<const float4*>(
                   g_xw + (size_t)d * OUT_CH + lane * 4);
    float* o = out + (size_t)s * OUT_CH + lane * 4;
    atomicAdd(o + 0, m.x * v);
    atomicAdd(o + 1, m.y * v);
    atomicAdd(o + 2, m.z * v);
    atomicAdd(o + 3, m.w * v);
}

// ---------------------------------------------------------------------------
// Launch
// inputs (metadata order): x[f32 N*256], edge_src[i32 E], edge_dst[i32 E],
//                          edge_vals[f32 E], weight[f32 256*128], bias[f32 128]
// output: f32 N*128
// ---------------------------------------------------------------------------
extern "C" void kernel_launch(void* const* d_in, const int* in_sizes, int n_in,
                              void* d_out, int out_size) {
    const float* x    = (const float*)d_in[0];
    const int*   esrc = (const int*)d_in[1];
    const int*   edst = (const int*)d_in[2];
    const float* eval = (const float*)d_in[3];
    const float* w    = (const float*)d_in[4];
    const float* bias = (const float*)d_in[5];
    float*       out  = (float*)d_out;

    const int N = in_sizes[0] / IN_CH;   // 100000
    const int E = in_sizes[1];           // 3200000

    // 1) out = bias (broadcast); d_out is poisoned, must init.
    int n4 = N * (OUT_CH / 4);
    init_out_kernel<<<(n4 + 255) / 256, 256>>>(
        (float4*)out, (const float4*)bias, n4);

    // 2) g_xw = x @ W
    gemm_kernel<<<(N + BM - 1) / BM, 256>>>(x, w, N);

    // 3) out[src] += xw[dst] * val  (atomic scatter, warp per edge)
    int warps = E;
    scatter_kernel<<<(warps + 7) / 8, 256>>>(esrc, edst, eval, out, E);
}

// round 14
// speedup vs baseline: 1.0114x; 1.0084x over previous
#include <cuda_runtime.h>
#include <cstddef>

#define N_NODES_MAX 100000
#define IN_CH 256
#define OUT_CH 128

// Scratch for xw = x @ W  (51.2 MB, static device array: no allocations)
__device__ float g_xw[(size_t)N_NODES_MAX * OUT_CH];

// ---------------------------------------------------------------------------
// Kernel 1: out[n, c] = bias[c]
// ---------------------------------------------------------------------------
__global__ void init_out_kernel(float4* __restrict__ out,
                                const float4* __restrict__ bias, int n4) {
    int i = blockIdx.x * blockDim.x + threadIdx.x;
    if (i < n4) out[i] = bias[i & (OUT_CH / 4 - 1)];
}

// ---------------------------------------------------------------------------
// Kernel 2: g_xw = x @ W   (M x 256) @ (256 x 128), fp32
// Tile: BM=64, BN=128, BK=32. 256 threads, each computes 8x4.
// A-tile stored transposed [BK][BM] with XOR swizzle on the row index so that
// the transposed scalar stores are bank-conflict-free while reads stay
// float4-aligned warp-uniform broadcasts.
// ---------------------------------------------------------------------------
#define BM 64
#define BN 128
#define BK 32

__global__ __launch_bounds__(256, 2) void gemm_kernel(
    const float* __restrict__ x, const float* __restrict__ w, int M) {
    __shared__ __align__(16) float As[BK][BM];
    __shared__ __align__(16) float Bs[BK][BN];

    const int t  = threadIdx.x;
    const int tx = t & 31;   // column group (4 cols each)
    const int ty = t >> 5;   // row group (8 rows each)
    const int m0 = blockIdx.x * BM;

    float acc[8][4];
#pragma unroll
    for (int i = 0; i < 8; i++)
#pragma unroll
        for (int j = 0; j < 4; j++) acc[i][j] = 0.f;

    for (int kt = 0; kt < IN_CH; kt += BK) {
        // ---- load x tile: 64 rows x 32 k-values, transposed+swizzled into As
#pragma unroll
        for (int s = 0; s < 2; s++) {
            int idx = t + s * 256;          // 0..511
            int r   = idx >> 3;             // 0..63  (row within tile)
            int c4  = idx & 7;              // 0..7   (float4 index along k)
            float4 v = make_float4(0.f, 0.f, 0.f, 0.f);
            int gr = m0 + r;
            if (gr < M)
                v = *reinterpret_cast<const float4*>(
                        x + (size_t)gr * IN_CH + kt + c4 * 4);
            // element (k = c4*4+q, row r) stored at As[k][ r ^ ((k>>2)<<2) ]
            int col = r ^ (c4 << 2);
            As[c4 * 4 + 0][col] = v.x;
            As[c4 * 4 + 1][col] = v.y;
            As[c4 * 4 + 2][col] = v.z;
            As[c4 * 4 + 3][col] = v.w;
        }
        // ---- load w tile: 32 k-rows x 128 cols (natural layout)
#pragma unroll
        for (int s = 0; s < 4; s++) {
            int idx = t + s * 256;          // 0..1023
            int kk  = idx >> 5;             // 0..31
            int q   = idx & 31;             // 0..31 (float4 index along n)
            *reinterpret_cast<float4*>(&Bs[kk][q * 4]) =
                *reinterpret_cast<const float4*>(
                    w + (size_t)(kt + kk) * OUT_CH + q * 4);
        }
        __syncthreads();

#pragma unroll
        for (int kk = 0; kk < BK; kk++) {
            int sw = (kk >> 2) << 2;  // swizzle term, 0..28 (bits 2..4)
            float4 a0 = *reinterpret_cast<const float4*>(
                            &As[kk][(ty * 8 + 0) ^ sw]);
            float4 a1 = *reinterpret_cast<const float4*>(
                            &As[kk][(ty * 8 + 4) ^ sw]);
            float4 b  = *reinterpret_cast<const float4*>(&Bs[kk][tx * 4]);
            float a[8] = {a0.x, a0.y, a0.z, a0.w, a1.x, a1.y, a1.z, a1.w};
#pragma unroll
            for (int i = 0; i < 8; i++) {
                acc[i][0] += a[i] * b.x;
                acc[i][1] += a[i] * b.y;
                acc[i][2] += a[i] * b.z;
                acc[i][3] += a[i] * b.w;
            }
        }
        __syncthreads();
    }

#pragma unroll
    for (int i = 0; i < 8; i++) {
        int gr = m0 + ty * 8 + i;
        if (gr < M)
            *reinterpret_cast<float4*>(g_xw + (size_t)gr * OUT_CH + tx * 4) =
                make_float4(acc[i][0], acc[i][1], acc[i][2], acc[i][3]);
    }
}

// ---------------------------------------------------------------------------
// Kernel 3: edge scatter. One warp per edge: gather xw[dst] (512B coalesced,
// L2-resident), scale by edge_val, RED.E.ADD.F32 into out[src].
// ---------------------------------------------------------------------------
__global__ __launch_bounds__(256) void scatter_kernel(
    const int* __restrict__ esrc, const int* __restrict__ edst,
    const float* __restrict__ eval, float* __restrict__ out, int E) {
    int e = (blockIdx.x * blockDim.x + threadIdx.x) >> 5;
    if (e >= E) return;
    int lane = threadIdx.x & 31;

    int   s = __ldg(esrc + e);
    int   d = __ldg(edst + e);
    float v = __ldg(eval + e);

    float4 m = *reinterpret_cast<const float4*>(
                   g_xw + (size_t)d * OUT_CH + lane * 4);
    float* o = out + (size_t)s * OUT_CH + lane * 4;
    atomicAdd(o + 0, m.x * v);
    atomicAdd(o + 1, m.y * v);
    atomicAdd(o + 2, m.z * v);
    atomicAdd(o + 3, m.w * v);
}

// ---------------------------------------------------------------------------
// Launch
// inputs (metadata order): x[f32 N*256], edge_src[i32 E], edge_dst[i32 E],
//                          edge_vals[f32 E], weight[f32 256*128], bias[f32 128]
// output: f32 N*128
// ---------------------------------------------------------------------------
extern "C" void kernel_launch(void* const* d_in, const int* in_sizes, int n_in,
                              void* d_out, int out_size) {
    const float* x    = (const float*)d_in[0];
    const int*   esrc = (const int*)d_in[1];
    const int*   edst = (const int*)d_in[2];
    const float* eval = (const float*)d_in[3];
    const float* w    = (const float*)d_in[4];
    const float* bias = (const float*)d_in[5];
    float*       out  = (float*)d_out;

    const int N = in_sizes[0] / IN_CH;   // 100000
    const int E = in_sizes[1];           // 3200000

    // 1) out = bias (broadcast); d_out is poisoned, must init.
    int n4 = N * (OUT_CH / 4);
    init_out_kernel<<<(n4 + 255) / 256, 256>>>(
        (float4*)out, (const float4*)bias, n4);

    // 2) g_xw = x @ W
    gemm_kernel<<<(N + BM - 1) / BM, 256>>>(x, w, N);

    // 3) out[src] += xw[dst] * val  (atomic scatter, warp per edge)
    int warps = E;
    scatter_kernel<<<(warps + 7) / 8, 256>>>(esrc, edst, eval, out, E);
}

// round 17
// speedup vs baseline: 1.8968x; 1.8754x over previous
#include <cuda_runtime.h>
#include <cstddef>

#define N_NODES_MAX 100000
#define IN_CH 256
#define OUT_CH 128

// Scratch for xw = x @ W  (51.2 MB, static device array: no allocations)
__device__ float g_xw[(size_t)N_NODES_MAX * OUT_CH];

// ---------------------------------------------------------------------------
// Kernel 1: out[n, c] = bias[c]
// ---------------------------------------------------------------------------
__global__ void init_out_kernel(float4* __restrict__ out,
                                const float4* __restrict__ bias, int n4) {
    int i = blockIdx.x * blockDim.x + threadIdx.x;
    if (i < n4) out[i] = bias[i & (OUT_CH / 4 - 1)];
}

// ---------------------------------------------------------------------------
// Kernel 2: g_xw = x @ W   (M x 256) @ (256 x 128), fp32
// Tile: BM=64, BN=128, BK=32. 256 threads, each computes 8x4.
// ---------------------------------------------------------------------------
#define BM 64
#define BN 128
#define BK 32

__global__ __launch_bounds__(256, 2) void gemm_kernel(
    const float* __restrict__ x, const float* __restrict__ w, int M) {
    __shared__ __align__(16) float As[BK][BM];
    __shared__ __align__(16) float Bs[BK][BN];

    const int t  = threadIdx.x;
    const int tx = t & 31;   // column group (4 cols each)
    const int ty = t >> 5;   // row group (8 rows each)
    const int m0 = blockIdx.x * BM;

    float acc[8][4];
#pragma unroll
    for (int i = 0; i < 8; i++)
#pragma unroll
        for (int j = 0; j < 4; j++) acc[i][j] = 0.f;

    for (int kt = 0; kt < IN_CH; kt += BK) {
        // ---- load x tile: 64 rows x 32 k-values, transposed+swizzled into As
#pragma unroll
        for (int s = 0; s < 2; s++) {
            int idx = t + s * 256;          // 0..511
            int r   = idx >> 3;             // 0..63  (row within tile)
            int c4  = idx & 7;              // 0..7   (float4 index along k)
            float4 v = make_float4(0.f, 0.f, 0.f, 0.f);
            int gr = m0 + r;
            if (gr < M)
                v = *reinterpret_cast<const float4*>(
                        x + (size_t)gr * IN_CH + kt + c4 * 4);
            int col = r ^ (c4 << 2);
            As[c4 * 4 + 0][col] = v.x;
            As[c4 * 4 + 1][col] = v.y;
            As[c4 * 4 + 2][col] = v.z;
            As[c4 * 4 + 3][col] = v.w;
        }
        // ---- load w tile: 32 k-rows x 128 cols (natural layout)
#pragma unroll
        for (int s = 0; s < 4; s++) {
            int idx = t + s * 256;          // 0..1023
            int kk  = idx >> 5;             // 0..31
            int q   = idx & 31;             // 0..31 (float4 index along n)
            *reinterpret_cast<float4*>(&Bs[kk][q * 4]) =
                *reinterpret_cast<const float4*>(
                    w + (size_t)(kt + kk) * OUT_CH + q * 4);
        }
        __syncthreads();

#pragma unroll
        for (int kk = 0; kk < BK; kk++) {
            int sw = (kk >> 2) << 2;  // swizzle term, bits 2..4
            float4 a0 = *reinterpret_cast<const float4*>(
                            &As[kk][(ty * 8 + 0) ^ sw]);
            float4 a1 = *reinterpret_cast<const float4*>(
                            &As[kk][(ty * 8 + 4) ^ sw]);
            float4 b  = *reinterpret_cast<const float4*>(&Bs[kk][tx * 4]);
            float a[8] = {a0.x, a0.y, a0.z, a0.w, a1.x, a1.y, a1.z, a1.w};
#pragma unroll
            for (int i = 0; i < 8; i++) {
                acc[i][0] += a[i] * b.x;
                acc[i][1] += a[i] * b.y;
                acc[i][2] += a[i] * b.z;
                acc[i][3] += a[i] * b.w;
            }
        }
        __syncthreads();
    }

#pragma unroll
    for (int i = 0; i < 8; i++) {
        int gr = m0 + ty * 8 + i;
        if (gr < M)
            *reinterpret_cast<float4*>(g_xw + (size_t)gr * OUT_CH + tx * 4) =
                make_float4(acc[i][0], acc[i][1], acc[i][2], acc[i][3]);
    }
}

// ---------------------------------------------------------------------------
// Kernel 3: edge scatter. One warp per edge: gather xw[dst] (512B coalesced,
// L2-resident), scale by edge_val, ONE vector red.global.add.v4.f32 per lane
// into out[src]. 4x fewer RED ops than scalar atomicAdd; same bytes.
// ---------------------------------------------------------------------------
__device__ __forceinline__ void red_add_v4(float* addr, float a, float b,
                                           float c, float d) {
    asm volatile("red.global.add.v4.f32 [%0], {%1, %2, %3, %4};"
                 :: "l"(addr), "f"(a), "f"(b), "f"(c), "f"(d)
                 : "memory");
}

__global__ __launch_bounds__(256) void scatter_kernel(
    const int* __restrict__ esrc, const int* __restrict__ edst,
    const float* __restrict__ eval, float* __restrict__ out, int E) {
    int e = (blockIdx.x * blockDim.x + threadIdx.x) >> 5;
    if (e >= E) return;
    int lane = threadIdx.x & 31;

    int   s = __ldg(esrc + e);
    int   d = __ldg(edst + e);
    float v = __ldg(eval + e);

    float4 m = *reinterpret_cast<const float4*>(
                   g_xw + (size_t)d * OUT_CH + lane * 4);
    float* o = out + (size_t)s * OUT_CH + lane * 4;   // 16B-aligned
    red_add_v4(o, m.x * v, m.y * v, m.z * v, m.w * v);
}

// ---------------------------------------------------------------------------
// Launch
// inputs (metadata order): x[f32 N*256], edge_src[i32 E], edge_dst[i32 E],
//                          edge_vals[f32 E], weight[f32 256*128], bias[f32 128]
// output: f32 N*128
// ---------------------------------------------------------------------------
extern "C" void kernel_launch(void* const* d_in, const int* in_sizes, int n_in,
                              void* d_out, int out_size) {
    const float* x    = (const float*)d_in[0];
    const int*   esrc = (const int*)d_in[1];
    const int*   edst = (const int*)d_in[2];
    const float* eval = (const float*)d_in[3];
    const float* w    = (const float*)d_in[4];
    const float* bias = (const float*)d_in[5];
    float*       out  = (float*)d_out;

    const int N = in_sizes[0] / IN_CH;   // 100000
    const int E = in_sizes[1];           // 3200000

    // 1) out = bias (broadcast); d_out is poisoned, must init.
    int n4 = N * (OUT_CH / 4);
    init_out_kernel<<<(n4 + 255) / 256, 256>>>(
        (float4*)out, (const float4*)bias, n4);

    // 2) g_xw = x @ W
    gemm_kernel<<<(N + BM - 1) / BM, 256>>>(x, w, N);

    // 3) out[src] += xw[dst] * val  (vector RED scatter, warp per edge)
    int warps = E;
    scatter_kernel<<<(warps + 7) / 8, 256>>>(esrc, edst, eval, out, E);
}